// round 8
// baseline (speedup 1.0000x reference)
#include <cuda_runtime.h>

// DynamicPatching: B=32, C=64, T=8192, S=64.
// out[b][s][c][p] = (p < len_bs) ? tensor[b][c][start_bs + p] : 0
// Output (B, S, C, max_len) row-major.
//
// Region-split formulation: each row = [len valid | pad zeros].
//  - full copy chunks: 4 unpredicated ld.cs + st.cs.128 (no per-elem ISETP)
//  - one mixed chunk per row: elementwise (<=4)
//  - zero chunks: store-only STG.128 stream (no loads, no compares)
// Hot loops keep the two-phase pattern: all loads for 4 rows batched before
// any store (MLP ~16 per thread).

#define PB 32
#define PC 64
#define PT 8192
#define PS 64

__device__ __forceinline__ float ldcs(const float* p) {
    float v;
    asm volatile("ld.global.cs.f32 %0, [%1];" : "=f"(v) : "l"(p));
    return v;
}
__device__ __forceinline__ void stcs4(float* p, float4 v) {
    asm volatile("st.global.cs.v4.f32 [%0], {%1,%2,%3,%4};"
                 :: "l"(p), "f"(v.x), "f"(v.y), "f"(v.z), "f"(v.w) : "memory");
}

__global__ void __launch_bounds__(256)
dynamic_patching_kernel(const float* __restrict__ tensor,
                        const int*   __restrict__ cps,   // (B, S+1) int32
                        float*       __restrict__ out,
                        int max_len)
{
    // 2 blocks per (b,s): each block covers 32 of the 64 channels.
    const int bs   = blockIdx.x >> 1;
    const int half = blockIdx.x & 1;
    const int b    = bs >> 6;            // / PS
    const int s    = bs & (PS - 1);      // % PS

    const int start = __ldg(cps + b * (PS + 1) + s);
    const int len   = __ldg(cps + b * (PS + 1) + s + 1) - start;

    const int wid  = threadIdx.x >> 5;   // 0..7
    const int lane = threadIdx.x & 31;
    const int c0   = half * 32 + wid * 4;          // warp's first channel

    const float* __restrict__ srcB =
        tensor + ((size_t)b * PC + c0) * PT + start;
    const long long dbase =
        ((long long)bs * PC + c0) * (long long)max_len;
    float* __restrict__ dstB = out + dbase;

    // Per-row region bounds.
    //  a[r]  : head count to reach 16B alignment (0..3)
    //  nc[r] : # fully-valid aligned float4 chunks
    //  nz[r] : # fully-zero aligned float4 chunks (after the mixed chunk)
    int a[4], nc[4], nz[4];
    int ncmax = 0, nzmax = 0;
    #pragma unroll
    for (int r = 0; r < 4; ++r) {
        a[r] = (int)((4 - ((dbase + (long long)r * max_len) & 3)) & 3);
        const int body = len - a[r];
        nc[r] = (body > 0) ? (body >> 2) : 0;
        const int zb = a[r] + (nc[r] << 2) + 4;     // first pure-zero chunk pos
        nz[r] = (max_len - zb >= 0) ? ((max_len - zb) >> 2) : 0;
        ncmax = max(ncmax, nc[r]);
        nzmax = max(nzmax, nz[r]);
    }

    // Edge scalars per row: head (<4), mixed chunk (<=4), tail (<4).
    #pragma unroll
    for (int r = 0; r < 4; ++r) {
        const long long drow = (long long)r * max_len;
        const float* sr = srcB + r * PT;
        if (lane < a[r])
            dstB[drow + lane] = (lane < len) ? ldcs(sr + lane) : 0.0f;
        const int pm = a[r] + (nc[r] << 2);          // mixed chunk start
        if (lane < 4) {
            const int p = pm + lane;
            if (p < max_len)
                dstB[drow + p] = (p < len) ? ldcs(sr + p) : 0.0f;
            const int pt = pm + 4 + (nz[r] << 2) + lane;   // tail (always pad)
            if (pt < max_len)
                dstB[drow + pt] = 0.0f;
        }
    }

    // Copy loop: phase 1 = 16 unpredicated loads across 4 rows, phase 2 = stores.
    for (int kb = 0; kb < ncmax; kb += 32) {
        const int k = kb + lane;
        float4 v[4];
        #pragma unroll
        for (int r = 0; r < 4; ++r) {
            if (k < nc[r]) {
                const float* sp = srcB + r * PT + a[r] + (k << 2);
                v[r].x = ldcs(sp + 0);
                v[r].y = ldcs(sp + 1);
                v[r].z = ldcs(sp + 2);
                v[r].w = ldcs(sp + 3);
            }
        }
        #pragma unroll
        for (int r = 0; r < 4; ++r) {
            if (k < nc[r])
                stcs4(dstB + (long long)r * max_len + a[r] + (k << 2), v[r]);
        }
    }

    // Zero loop: pure STG.128 stream.
    const float4 z4 = make_float4(0.0f, 0.0f, 0.0f, 0.0f);
    for (int kb = 0; kb < nzmax; kb += 32) {
        const int k = kb + lane;
        #pragma unroll
        for (int r = 0; r < 4; ++r) {
            if (k < nz[r]) {
                const int p = a[r] + (nc[r] << 2) + 4 + (k << 2);
                stcs4(dstB + (long long)r * max_len + p, z4);
            }
        }
    }
}

extern "C" void kernel_launch(void* const* d_in, const int* in_sizes, int n_in,
                              void* d_out, int out_size)
{
    const float* tensor = (const float*)d_in[0];
    const int*   cps    = (const int*)d_in[1];
    float*       out    = (float*)d_out;

    const int max_len = out_size / (PB * PS * PC);

    dynamic_patching_kernel<<<PB * PS * 2, 256>>>(tensor, cps, out, max_len);
}